// round 15
// baseline (speedup 1.0000x reference)
#include <cuda_runtime.h>
#include <math.h>

#define B  8
#define C  48
#define HH 192
#define WW 192
#define NN (HH*WW)   // 36864

// ---------------- scratch (no allocations allowed) ----------------
__device__ float  g_G[4*B*C*C];        // Gram matrices  [s][b][c][d]
__device__ float  g_Pt[B*4*C*C];       // P row-major    [b][s][co][e]
__device__ float  g_y1[B*C*NN];        // fuse output; overwritten with t by k_pre
__device__ double g_stats[4*C];        // sum1, sq1, sum2, sq2
__device__ float  g_bn[4*C];           // scale1, shift1, scale2, shift2

__device__ __forceinline__ float dot48(const float* __restrict__ a, const float* __restrict__ b) {
    float s = 0.f;
    #pragma unroll
    for (int k = 0; k < 12; k++) {
        const float4 x = ((const float4*)a)[k];
        const float4 y = ((const float4*)b)[k];
        s += x.x*y.x + x.y*y.y + x.z*y.z + x.w*y.w;
    }
    return s;
}

// ---------------- tf32 helpers (verified R7/R14) ----------------
__device__ __forceinline__ void split_tf32(float x, unsigned& hi, unsigned& lo) {
    unsigned h;
    asm("cvt.rna.tf32.f32 %0, %1;" : "=r"(h) : "f"(x));
    float r = x - __uint_as_float(h);
    unsigned l;
    asm("cvt.rna.tf32.f32 %0, %1;" : "=r"(l) : "f"(r));
    hi = h; lo = l;
}
__device__ __forceinline__ void mma_tf32(float d[4], const unsigned a[4], const unsigned b[2]) {
    asm volatile(
        "mma.sync.aligned.m16n8k8.row.col.f32.tf32.tf32.f32 "
        "{%0,%1,%2,%3}, {%4,%5,%6,%7}, {%8,%9}, {%0,%1,%2,%3};"
        : "+f"(d[0]), "+f"(d[1]), "+f"(d[2]), "+f"(d[3])
        : "r"(a[0]), "r"(a[1]), "r"(a[2]), "r"(a[3]), "r"(b[0]), "r"(b[1]));
}

// ---------------- zero scratch ----------------
__global__ void k_zero() {
    int i = blockIdx.x * 256 + threadIdx.x;
    if (i < 4*B*C*C) g_G[i] = 0.f;
    if (i < 4*C)     g_stats[i] = 0.0;
}

// ---------------- pass A: Gram via tf32 mma.sync (R14 proven) ----------------
__global__ __launch_bounds__(384) void k_gram(const float* __restrict__ xa,
                                              const float* __restrict__ xb,
                                              const float* __restrict__ xc,
                                              const float* __restrict__ xd) {
    __shared__ float sX[4*48*52];   // 39936 B
    const int b     = blockIdx.y;
    const int chunk = blockIdx.x;   // 16 chunks of 2304
    const int tid  = threadIdx.x;
    const int warp = tid >> 5, lane = tid & 31;
    const int g = lane >> 2, t = lane & 3;
    const int s   = warp / 3;
    const int nt2 = (warp - s*3) * 2;

    float acc[3][2][4];
    #pragma unroll
    for (int m = 0; m < 3; m++)
        #pragma unroll
        for (int j = 0; j < 2; j++)
            #pragma unroll
            for (int k = 0; k < 4; k++) acc[m][j][k] = 0.f;

    const size_t base = (size_t)b * C * NN + (size_t)chunk * 2304;
    const float* src[4] = {xa, xb, xc, xd};

    float r[24];
    #pragma unroll
    for (int k = 0; k < 24; k++) {
        const int idx = tid + 384*k;
        const int s2 = idx / 2304, rem = idx - s2*2304;
        const int c = rem / 48, nl = rem - c*48;
        r[k] = src[s2][base + (size_t)c * NN + nl];
    }

    const float* A  = sX;
    const float* Bm = sX + s*2496;

    for (int tile = 0; tile < 48; tile++) {
        __syncthreads();
        #pragma unroll
        for (int k = 0; k < 24; k++) {
            const int idx = tid + 384*k;
            const int s2 = idx / 2304, rem = idx - s2*2304;
            const int c = rem / 48, nl = rem - c*48;
            sX[(s2*48 + c)*52 + nl] = r[k];
        }
        __syncthreads();
        if (tile < 47) {
            const int n0 = (tile + 1) * 48;
            #pragma unroll
            for (int k = 0; k < 24; k++) {
                const int idx = tid + 384*k;
                const int s2 = idx / 2304, rem = idx - s2*2304;
                const int c = rem / 48, nl = rem - c*48;
                r[k] = src[s2][base + (size_t)c * NN + n0 + nl];
            }
        }
        for (int k8 = 0; k8 < 6; k8++) {
            const int k0 = k8 * 8;
            unsigned ahi[3][4], alo[3][4];
            #pragma unroll
            for (int m = 0; m < 3; m++) {
                split_tf32(A[(16*m + g    )*52 + k0 + t    ], ahi[m][0], alo[m][0]);
                split_tf32(A[(16*m + g + 8)*52 + k0 + t    ], ahi[m][1], alo[m][1]);
                split_tf32(A[(16*m + g    )*52 + k0 + t + 4], ahi[m][2], alo[m][2]);
                split_tf32(A[(16*m + g + 8)*52 + k0 + t + 4], ahi[m][3], alo[m][3]);
            }
            unsigned bhi[2][2], blo[2][2];
            #pragma unroll
            for (int j = 0; j < 2; j++) {
                const int dr = 8*(nt2 + j) + g;
                split_tf32(Bm[dr*52 + k0 + t    ], bhi[j][0], blo[j][0]);
                split_tf32(Bm[dr*52 + k0 + t + 4], bhi[j][1], blo[j][1]);
            }
            #pragma unroll
            for (int m = 0; m < 3; m++)
                #pragma unroll
                for (int j = 0; j < 2; j++) {
                    mma_tf32(acc[m][j], alo[m], bhi[j]);
                    mma_tf32(acc[m][j], ahi[m], blo[j]);
                    mma_tf32(acc[m][j], ahi[m], bhi[j]);
                }
        }
    }
    #pragma unroll
    for (int m = 0; m < 3; m++)
        #pragma unroll
        for (int j = 0; j < 2; j++) {
            const int c0 = 16*m + g;
            const int d0 = 8*(nt2 + j) + 2*t;
            float* Gp = &g_G[((size_t)(s*B + b)*48)*48];
            atomicAdd(&Gp[ c0     *48 + d0    ], acc[m][j][0]);
            atomicAdd(&Gp[ c0     *48 + d0 + 1], acc[m][j][1]);
            atomicAdd(&Gp[(c0 + 8)*48 + d0    ], acc[m][j][2]);
            atomicAdd(&Gp[(c0 + 8)*48 + d0 + 1], acc[m][j][3]);
        }
}

// ---------------- pass B: energy -> attention -> M -> P — float4 inner-product version ----------------
__global__ __launch_bounds__(256) void k_attn(const float* __restrict__ Wa,
                                              const float* __restrict__ Wb,
                                              const float* __restrict__ Wc,
                                              const float* __restrict__ Wd,
                                              const float* __restrict__ fuse_w) {
    __shared__ float sA[48*52];
    __shared__ float sB[48*52];
    __shared__ float sC[48*52];
    __shared__ float sD[48*52];
    const int s = blockIdx.x, b = blockIdx.y, tid = threadIdx.x;
    const float* Wsp = (s == 0) ? Wa : (s == 1) ? Wb : (s == 2) ? Wc : Wd;

    for (int i = tid; i < 2304; i += 256) {
        const int r = i / 48, q = i - r*48;
        sA[r*52+q] = g_G[(s*B + b)*2304 + i];
        sB[r*52+q] = Wa[i];
        sC[r*52+q] = Wsp[i];
    }
    __syncthreads();
    for (int i = tid; i < 2304; i += 256) {
        const int e = i / 48, d = i - e*48;
        sD[d*52+e] = dot48(&sA[e*52], &sC[d*52]);
    }
    __syncthreads();
    for (int i = tid; i < 2304; i += 256) {
        const int c = i / 48, d = i - c*48;
        sA[c*52+d] = dot48(&sB[c*52], &sD[d*52]);
    }
    __syncthreads();
    if (tid < 48) {
        const int c = tid;
        float mn = sA[c*52];
        for (int d = 1; d < 48; d++) mn = fminf(mn, sA[c*52+d]);
        float sum = 0.f;
        for (int d = 0; d < 48; d++) { const float v = expf(mn - sA[c*52+d]); sD[d*52+c] = v; sum += v; }
        const float inv = 1.f / sum;
        for (int d = 0; d < 48; d++) sD[d*52+c] *= inv;
    }
    for (int i = tid; i < 2304; i += 256) {
        const int co = i / 48, c = i - co*48;
        sB[co*52+c] = fuse_w[co*192 + s*48 + c];
    }
    __syncthreads();
    for (int i = tid; i < 2304; i += 256) {
        const int co = i / 48, d = i - co*48;
        sA[co*52+d] = dot48(&sB[co*52], &sD[d*52]);
    }
    __syncthreads();
    for (int i = tid; i < 2304; i += 256) {
        const int d = i / 48, e = i - d*48;
        sB[e*52+d] = sC[d*52+e];
    }
    __syncthreads();
    // P[co][e] stored ROW-MAJOR for mma A operand
    for (int i = tid; i < 2304; i += 256) {
        const int co = i / 48, e = i - co*48;
        g_Pt[(((size_t)b*4 + s)*48 + co)*48 + e] = dot48(&sA[co*52], &sB[e*52]);
    }
}

// ---------------- pass C: fused 1x1 conv via tf32 mma.sync ----------------
// block: 384 threads / 12 warps; tile 48co x 192n; K=192 in 4 chunks of 48 (per source).
// warp -> 3 m16 tiles x 2 n8 tiles (cols warp*16 + {0,8}).
__global__ __launch_bounds__(384) void k_fuse(const float* __restrict__ xa,
                                              const float* __restrict__ xb,
                                              const float* __restrict__ xc,
                                              const float* __restrict__ xd,
                                              const float* __restrict__ fuse_b) {
    __shared__ float sWm[48*52];     // [co][e]  9984 B, stride 52
    __shared__ float sX[48*200];     // [e][n]  38400 B, stride 200
    __shared__ float sstats[96];
    const int b  = blockIdx.y;
    const int n0 = blockIdx.x * 192;
    const int tid = threadIdx.x;
    const int warp = tid >> 5, lane = tid & 31;
    const int r = lane >> 2, q = lane & 3;

    if (tid < 96) sstats[tid] = 0.f;

    float acc[3][2][4];
    #pragma unroll
    for (int m = 0; m < 3; m++)
        #pragma unroll
        for (int nt = 0; nt < 2; nt++)
            #pragma unroll
            for (int k = 0; k < 4; k++) acc[m][nt][k] = 0.f;

    const float* src[4] = {xa, xb, xc, xd};
    const float* ptb = &g_Pt[(size_t)b*4*2304];

    // register-prefetch staging: X 9216/384 = 24 per thread, W 2304/384 = 6 per thread
    float xr[24];
    #pragma unroll
    for (int k = 0; k < 24; k++) {
        const int idx = tid + 384*k;
        const int e = idx / 192, n = idx - e*192;
        xr[k] = src[0][((size_t)b*48 + e)*NN + n0 + n];
    }
    float wr[6];
    #pragma unroll
    for (int j = 0; j < 6; j++) wr[j] = ptb[tid + 384*j];

    for (int s = 0; s < 4; s++) {
        __syncthreads();   // previous chunk's consumers done
        #pragma unroll
        for (int k = 0; k < 24; k++) {
            const int idx = tid + 384*k;
            const int e = idx / 192, n = idx - e*192;
            sX[e*200 + n] = xr[k];
        }
        #pragma unroll
        for (int j = 0; j < 6; j++) {
            const int idx = tid + 384*j;
            const int co = idx / 48, e = idx - co*48;
            sWm[co*52 + e] = wr[j];
        }
        __syncthreads();   // smem ready
        if (s < 3) {
            const float* nf = src[s + 1];
            #pragma unroll
            for (int k = 0; k < 24; k++) {
                const int idx = tid + 384*k;
                const int e = idx / 192, n = idx - e*192;
                xr[k] = nf[((size_t)b*48 + e)*NN + n0 + n];
            }
            #pragma unroll
            for (int j = 0; j < 6; j++) wr[j] = ptb[(s + 1)*2304 + tid + 384*j];
        }
        for (int k8 = 0; k8 < 6; k8++) {
            const int k0 = k8 * 8;
            unsigned ahi[3][4], alo[3][4];
            #pragma unroll
            for (int m = 0; m < 3; m++) {
                split_tf32(sWm[(16*m + r    )*52 + k0 + q    ], ahi[m][0], alo[m][0]);
                split_tf32(sWm[(16*m + r + 8)*52 + k0 + q    ], ahi[m][1], alo[m][1]);
                split_tf32(sWm[(16*m + r    )*52 + k0 + q + 4], ahi[m][2], alo[m][2]);
                split_tf32(sWm[(16*m + r + 8)*52 + k0 + q + 4], ahi[m][3], alo[m][3]);
            }
            unsigned bhi[2][2], blo[2][2];
            #pragma unroll
            for (int nt = 0; nt < 2; nt++) {
                const int cb = warp*16 + nt*8 + r;
                split_tf32(sX[(k0 + q    )*200 + cb], bhi[nt][0], blo[nt][0]);
                split_tf32(sX[(k0 + q + 4)*200 + cb], bhi[nt][1], blo[nt][1]);
            }
            #pragma unroll
            for (int m = 0; m < 3; m++)
                #pragma unroll
                for (int nt = 0; nt < 2; nt++) {
                    mma_tf32(acc[m][nt], alo[m], bhi[nt]);
                    mma_tf32(acc[m][nt], ahi[m], blo[nt]);
                    mma_tf32(acc[m][nt], ahi[m], bhi[nt]);
                }
        }
    }

    // epilogue (R7-verified D mapping): rows coA=16m+r, coB=coA+8; cols n0+warp*16+nt*8+2q (+1)
    #pragma unroll
    for (int m = 0; m < 3; m++) {
        const int coA = 16*m + r, coB = coA + 8;
        const float fbA = fuse_b[coA], fbB = fuse_b[coB];
        float sumA = 0.f, sqA = 0.f, sumB = 0.f, sqB = 0.f;
        #pragma unroll
        for (int nt = 0; nt < 2; nt++) {
            const int n = n0 + warp*16 + nt*8 + 2*q;
            const float vA0 = acc[m][nt][0] + fbA, vA1 = acc[m][nt][1] + fbA;
            const float vB0 = acc[m][nt][2] + fbB, vB1 = acc[m][nt][3] + fbB;
            *(float2*)&g_y1[((size_t)b*48 + coA)*NN + n] = make_float2(vA0, vA1);
            *(float2*)&g_y1[((size_t)b*48 + coB)*NN + n] = make_float2(vB0, vB1);
            sumA += vA0 + vA1; sqA += vA0*vA0 + vA1*vA1;
            sumB += vB0 + vB1; sqB += vB0*vB0 + vB1*vB1;
        }
        #pragma unroll
        for (int o = 1; o < 4; o <<= 1) {
            sumA += __shfl_xor_sync(0xffffffffu, sumA, o);
            sqA  += __shfl_xor_sync(0xffffffffu, sqA,  o);
            sumB += __shfl_xor_sync(0xffffffffu, sumB, o);
            sqB  += __shfl_xor_sync(0xffffffffu, sqB,  o);
        }
        if (q == 0) {
            atomicAdd(&sstats[coA], sumA); atomicAdd(&sstats[48 + coA], sqA);
            atomicAdd(&sstats[coB], sumB); atomicAdd(&sstats[48 + coB], sqB);
        }
    }
    __syncthreads();
    if (tid < 48) {
        atomicAdd(&g_stats[tid],      (double)sstats[tid]);
        atomicAdd(&g_stats[48 + tid], (double)sstats[48 + tid]);
    }
}

// ---------------- BN finalize (tiny) ----------------
__global__ void k_bnfin(const float* __restrict__ gamma, const float* __restrict__ beta, int which) {
    const int c = threadIdx.x;
    if (c >= 48) return;
    const double cnt  = (double)B * NN;
    const double mean = g_stats[which*96 + c] / cnt;
    const double var  = g_stats[which*96 + 48 + c] / cnt - mean*mean;
    const float  sc   = (float)((double)gamma[c] / sqrt(var + 1e-5));
    const float  sh   = beta[c] - (float)mean * sc;
    g_bn[which*96 + c]      = sc;
    g_bn[which*96 + 48 + c] = sh;
}

// ---------------- pass D: t = gamma_cam*relu(bn1(y1)) + input, in place into g_y1 ----------------
__global__ void k_pre(const float* __restrict__ inp, const float* __restrict__ gamma_cam) {
    const size_t i = ((size_t)blockIdx.x * 256 + threadIdx.x) * 4;
    const int co = (int)((i / NN) % 48);
    const float sc = g_bn[co], sh = g_bn[48 + co];
    const float gcam = gamma_cam[0];
    float4 y = *(float4*)(g_y1 + i);
    const float4 x = *(const float4*)(inp + i);
    y.x = gcam * fmaxf(y.x*sc + sh, 0.f) + x.x;
    y.y = gcam * fmaxf(y.y*sc + sh, 0.f) + x.y;
    y.z = gcam * fmaxf(y.z*sc + sh, 0.f) + x.z;
    y.w = gcam * fmaxf(y.w*sc + sh, 0.f) + x.w;
    *(float4*)(g_y1 + i) = y;
}

// ---------------- pass E: 3x3 conv with register double-buffered staging (R11 proven) ----------------
__global__ __launch_bounds__(256) void k_conv(const float* __restrict__ out_w,
                                              const float* __restrict__ out_b,
                                              float* __restrict__ out) {
    __shared__ float sW[48*9];
    __shared__ float sT[10*34];
    __shared__ float ssum[48], ssq[48];
    const int b   = blockIdx.z;
    const int hy0 = blockIdx.y * 8;
    const int wx0 = blockIdx.x * 32;
    const int tid = threadIdx.x;
    const int cg  = tid >> 6;
    const int p   = tid & 63;
    const int px  = p & 31;
    const int py2 = p >> 5;

    if (tid < 48) { ssum[tid] = 0.f; ssq[tid] = 0.f; }

    const int r0 = tid / 34, c0 = tid - r0*34;
    const int gh0 = hy0 + r0 - 1, gw0 = wx0 + c0 - 1;
    const bool ok0 = (gh0 >= 0 && gh0 < HH && gw0 >= 0 && gw0 < WW) && (tid < 340);
    const int off0 = ok0 ? (gh0*WW + gw0) : 0;
    const int i1 = tid + 256;
    const int r1 = i1 / 34, c1 = i1 - r1*34;
    const int gh1 = hy0 + r1 - 1, gw1 = wx0 + c1 - 1;
    const bool ok1 = (i1 < 340) && (gh1 >= 0 && gh1 < HH && gw1 >= 0 && gw1 < WW);
    const int off1 = ok1 ? (gh1*WW + gw1) : 0;
    const bool st1 = (i1 < 340);
    const int wco0 = tid / 9, wk0 = tid - wco0*9;
    const int wbase0 = wco0*432 + wk0;
    const int wco1 = i1 / 9, wk1 = i1 - wco1*9;
    const int wbase1 = wco1*432 + wk1;
    const bool wok1 = (i1 < 432);

    const float* tbase = g_y1 + (size_t)b*48*NN;

    float t0 = ok0 ? tbase[off0] : 0.f;
    float t1 = ok1 ? tbase[off1] : 0.f;
    float w0 = out_w[wbase0];
    float w1 = wok1 ? out_w[wbase1] : 0.f;

    float acc[48];
    #pragma unroll
    for (int i = 0; i < 48; i++) acc[i] = 0.f;

    for (int ci = 0; ci < 48; ci++) {
        __syncthreads();
        if (tid < 340) sT[tid] = t0;
        if (st1)       sT[i1]  = t1;
        sW[tid] = w0;
        if (wok1) sW[i1] = w1;
        __syncthreads();
        if (ci < 47) {
            const float* tp = tbase + (size_t)(ci + 1)*NN;
            t0 = ok0 ? tp[off0] : 0.f;
            t1 = ok1 ? tp[off1] : 0.f;
            w0 = out_w[wbase0 + (ci + 1)*9];
            w1 = wok1 ? out_w[wbase1 + (ci + 1)*9] : 0.f;
        }

        float v[6][3];
        const int baseRow = py2 * 4;
        #pragma unroll
        for (int rr = 0; rr < 6; rr++)
            #pragma unroll
            for (int cc = 0; cc < 3; cc++)
                v[rr][cc] = sT[(baseRow + rr)*34 + px + cc];

        #pragma unroll
        for (int j = 0; j < 12; j++) {
            const float* wp = &sW[(cg*12 + j)*9];
            const float q0=wp[0],q1=wp[1],q2=wp[2],q3=wp[3],q4=wp[4],q5=wp[5],q6=wp[6],q7=wp[7],q8=wp[8];
            #pragma unroll
            for (int r = 0; r < 4; r++) {
                acc[j*4 + r] += q0*v[r  ][0] + q1*v[r  ][1] + q2*v[r  ][2]
                              + q3*v[r+1][0] + q4*v[r+1][1] + q5*v[r+1][2]
                              + q6*v[r+2][0] + q7*v[r+2][1] + q8*v[r+2][2];
            }
        }
    }

    #pragma unroll
    for (int j = 0; j < 12; j++) {
        const int co = cg*12 + j;
        const float bo = out_b[co];
        float lsum = 0.f, lsq = 0.f;
        #pragma unroll
        for (int r = 0; r < 4; r++) {
            const float val = acc[j*4 + r] + bo;
            const int gh = hy0 + py2*4 + r, gw = wx0 + px;
            out[((size_t)b*48 + co)*NN + gh*WW + gw] = val;
            lsum += val; lsq += val*val;
        }
        for (int o = 16; o > 0; o >>= 1) {
            lsum += __shfl_down_sync(0xffffffffu, lsum, o);
            lsq  += __shfl_down_sync(0xffffffffu, lsq,  o);
        }
        if ((tid & 31) == 0) { atomicAdd(&ssum[co], lsum); atomicAdd(&ssq[co], lsq); }
    }
    __syncthreads();
    if (tid < 48) {
        atomicAdd(&g_stats[96 + tid],  (double)ssum[tid]);
        atomicAdd(&g_stats[144 + tid], (double)ssq[tid]);
    }
}

// ---------------- pass G: in-place relu(bn2(y2)) ----------------
__global__ void k_final(float* __restrict__ out) {
    const size_t i = ((size_t)blockIdx.x * 256 + threadIdx.x) * 4;
    const int co = (int)((i / NN) % 48);
    const float sc = g_bn[96 + co], sh = g_bn[144 + co];
    float4 v = *(float4*)(out + i);
    v.x = fmaxf(v.x*sc + sh, 0.f);
    v.y = fmaxf(v.y*sc + sh, 0.f);
    v.z = fmaxf(v.z*sc + sh, 0.f);
    v.w = fmaxf(v.w*sc + sh, 0.f);
    *(float4*)(out + i) = v;
}

// ---------------- launch ----------------
extern "C" void kernel_launch(void* const* d_in, const int* in_sizes, int n_in,
                              void* d_out, int out_size) {
    const float* xa         = (const float*)d_in[0];
    const float* fb         = (const float*)d_in[1];
    const float* fc         = (const float*)d_in[2];
    const float* fd         = (const float*)d_in[3];
    const float* Wa         = (const float*)d_in[4];
    const float* Wb         = (const float*)d_in[5];
    const float* Wc         = (const float*)d_in[6];
    const float* Wd         = (const float*)d_in[7];
    const float* fuse_w     = (const float*)d_in[8];
    const float* fuse_b     = (const float*)d_in[9];
    const float* fuse_gamma = (const float*)d_in[10];
    const float* fuse_beta  = (const float*)d_in[11];
    const float* gamma_cam  = (const float*)d_in[12];
    const float* out_w      = (const float*)d_in[13];
    const float* out_b      = (const float*)d_in[14];
    const float* out_gamma  = (const float*)d_in[15];
    const float* out_beta   = (const float*)d_in[16];
    float* out = (float*)d_out;

    k_zero<<<288, 256>>>();
    k_gram<<<dim3(16, B), 384>>>(xa, fb, fc, fd);
    k_attn<<<dim3(4, B), 256>>>(Wa, Wb, Wc, Wd, fuse_w);
    k_fuse<<<dim3(NN/192, B), 384>>>(xa, fb, fc, fd, fuse_b);
    k_bnfin<<<1, 48>>>(fuse_gamma, fuse_beta, 0);
    k_pre<<<(B*C*NN)/1024, 256>>>(xa, gamma_cam);
    k_conv<<<dim3(WW/32, HH/8, B), 256>>>(out_w, out_b, out);
    k_bnfin<<<1, 48>>>(out_gamma, out_beta, 1);
    k_final<<<(B*C*NN)/1024, 256>>>(out);
}

// round 16
// speedup vs baseline: 1.0131x; 1.0131x over previous
#include <cuda_runtime.h>
#include <math.h>

#define B  8
#define C  48
#define HH 192
#define WW 192
#define NN (HH*WW)   // 36864

// ---------------- scratch (no allocations allowed) ----------------
__device__ float  g_G[4*B*C*C];        // Gram matrices  [s][b][c][d]
__device__ float  g_Pt[B*4*C*C];       // P transposed   [b][s][e][co]
__device__ float  g_y1[B*C*NN];        // fuse output; overwritten with t by k_pre
__device__ double g_stats[4*C];        // sum1, sq1, sum2, sq2
__device__ float  g_bn[4*C];           // scale1, shift1, scale2, shift2

__device__ __forceinline__ float dot48(const float* __restrict__ a, const float* __restrict__ b) {
    float s = 0.f;
    #pragma unroll
    for (int k = 0; k < 12; k++) {
        const float4 x = ((const float4*)a)[k];
        const float4 y = ((const float4*)b)[k];
        s += x.x*y.x + x.y*y.y + x.z*y.z + x.w*y.w;
    }
    return s;
}

// ---------------- tf32 helpers (verified R7/R14) ----------------
__device__ __forceinline__ void split_tf32(float x, unsigned& hi, unsigned& lo) {
    unsigned h;
    asm("cvt.rna.tf32.f32 %0, %1;" : "=r"(h) : "f"(x));
    float r = x - __uint_as_float(h);
    unsigned l;
    asm("cvt.rna.tf32.f32 %0, %1;" : "=r"(l) : "f"(r));
    hi = h; lo = l;
}
__device__ __forceinline__ void mma_tf32(float d[4], const unsigned a[4], const unsigned b[2]) {
    asm volatile(
        "mma.sync.aligned.m16n8k8.row.col.f32.tf32.tf32.f32 "
        "{%0,%1,%2,%3}, {%4,%5,%6,%7}, {%8,%9}, {%0,%1,%2,%3};"
        : "+f"(d[0]), "+f"(d[1]), "+f"(d[2]), "+f"(d[3])
        : "r"(a[0]), "r"(a[1]), "r"(a[2]), "r"(a[3]), "r"(b[0]), "r"(b[1]));
}

// ---------------- zero scratch ----------------
__global__ void k_zero() {
    int i = blockIdx.x * 256 + threadIdx.x;
    if (i < 4*B*C*C) g_G[i] = 0.f;
    if (i < 4*C)     g_stats[i] = 0.0;
}

// ---------------- pass A: Gram via tf32 mma.sync (R14 proven) ----------------
__global__ __launch_bounds__(384) void k_gram(const float* __restrict__ xa,
                                              const float* __restrict__ xb,
                                              const float* __restrict__ xc,
                                              const float* __restrict__ xd) {
    __shared__ float sX[4*48*52];   // 39936 B
    const int b     = blockIdx.y;
    const int chunk = blockIdx.x;   // 16 chunks of 2304
    const int tid  = threadIdx.x;
    const int warp = tid >> 5, lane = tid & 31;
    const int g = lane >> 2, t = lane & 3;
    const int s   = warp / 3;
    const int nt2 = (warp - s*3) * 2;

    float acc[3][2][4];
    #pragma unroll
    for (int m = 0; m < 3; m++)
        #pragma unroll
        for (int j = 0; j < 2; j++)
            #pragma unroll
            for (int k = 0; k < 4; k++) acc[m][j][k] = 0.f;

    const size_t base = (size_t)b * C * NN + (size_t)chunk * 2304;
    const float* src[4] = {xa, xb, xc, xd};

    float r[24];
    #pragma unroll
    for (int k = 0; k < 24; k++) {
        const int idx = tid + 384*k;
        const int s2 = idx / 2304, rem = idx - s2*2304;
        const int c = rem / 48, nl = rem - c*48;
        r[k] = src[s2][base + (size_t)c * NN + nl];
    }

    const float* A  = sX;
    const float* Bm = sX + s*2496;

    for (int tile = 0; tile < 48; tile++) {
        __syncthreads();
        #pragma unroll
        for (int k = 0; k < 24; k++) {
            const int idx = tid + 384*k;
            const int s2 = idx / 2304, rem = idx - s2*2304;
            const int c = rem / 48, nl = rem - c*48;
            sX[(s2*48 + c)*52 + nl] = r[k];
        }
        __syncthreads();
        if (tile < 47) {
            const int n0 = (tile + 1) * 48;
            #pragma unroll
            for (int k = 0; k < 24; k++) {
                const int idx = tid + 384*k;
                const int s2 = idx / 2304, rem = idx - s2*2304;
                const int c = rem / 48, nl = rem - c*48;
                r[k] = src[s2][base + (size_t)c * NN + n0 + nl];
            }
        }
        for (int k8 = 0; k8 < 6; k8++) {
            const int k0 = k8 * 8;
            unsigned ahi[3][4], alo[3][4];
            #pragma unroll
            for (int m = 0; m < 3; m++) {
                split_tf32(A[(16*m + g    )*52 + k0 + t    ], ahi[m][0], alo[m][0]);
                split_tf32(A[(16*m + g + 8)*52 + k0 + t    ], ahi[m][1], alo[m][1]);
                split_tf32(A[(16*m + g    )*52 + k0 + t + 4], ahi[m][2], alo[m][2]);
                split_tf32(A[(16*m + g + 8)*52 + k0 + t + 4], ahi[m][3], alo[m][3]);
            }
            unsigned bhi[2][2], blo[2][2];
            #pragma unroll
            for (int j = 0; j < 2; j++) {
                const int dr = 8*(nt2 + j) + g;
                split_tf32(Bm[dr*52 + k0 + t    ], bhi[j][0], blo[j][0]);
                split_tf32(Bm[dr*52 + k0 + t + 4], bhi[j][1], blo[j][1]);
            }
            #pragma unroll
            for (int m = 0; m < 3; m++)
                #pragma unroll
                for (int j = 0; j < 2; j++) {
                    mma_tf32(acc[m][j], alo[m], bhi[j]);
                    mma_tf32(acc[m][j], ahi[m], blo[j]);
                    mma_tf32(acc[m][j], ahi[m], bhi[j]);
                }
        }
    }
    #pragma unroll
    for (int m = 0; m < 3; m++)
        #pragma unroll
        for (int j = 0; j < 2; j++) {
            const int c0 = 16*m + g;
            const int d0 = 8*(nt2 + j) + 2*t;
            float* Gp = &g_G[((size_t)(s*B + b)*48)*48];
            atomicAdd(&Gp[ c0     *48 + d0    ], acc[m][j][0]);
            atomicAdd(&Gp[ c0     *48 + d0 + 1], acc[m][j][1]);
            atomicAdd(&Gp[(c0 + 8)*48 + d0    ], acc[m][j][2]);
            atomicAdd(&Gp[(c0 + 8)*48 + d0 + 1], acc[m][j][3]);
        }
}

// ---------------- pass B: energy -> attention -> M -> P — float4 inner-product version ----------------
__global__ __launch_bounds__(256) void k_attn(const float* __restrict__ Wa,
                                              const float* __restrict__ Wb,
                                              const float* __restrict__ Wc,
                                              const float* __restrict__ Wd,
                                              const float* __restrict__ fuse_w) {
    __shared__ float sA[48*52];
    __shared__ float sB[48*52];
    __shared__ float sC[48*52];
    __shared__ float sD[48*52];
    const int s = blockIdx.x, b = blockIdx.y, tid = threadIdx.x;
    const float* Wsp = (s == 0) ? Wa : (s == 1) ? Wb : (s == 2) ? Wc : Wd;

    for (int i = tid; i < 2304; i += 256) {
        const int r = i / 48, q = i - r*48;
        sA[r*52+q] = g_G[(s*B + b)*2304 + i];
        sB[r*52+q] = Wa[i];
        sC[r*52+q] = Wsp[i];
    }
    __syncthreads();
    for (int i = tid; i < 2304; i += 256) {
        const int e = i / 48, d = i - e*48;
        sD[d*52+e] = dot48(&sA[e*52], &sC[d*52]);
    }
    __syncthreads();
    for (int i = tid; i < 2304; i += 256) {
        const int c = i / 48, d = i - c*48;
        sA[c*52+d] = dot48(&sB[c*52], &sD[d*52]);
    }
    __syncthreads();
    if (tid < 48) {
        const int c = tid;
        float mn = sA[c*52];
        for (int d = 1; d < 48; d++) mn = fminf(mn, sA[c*52+d]);
        float sum = 0.f;
        for (int d = 0; d < 48; d++) { const float v = expf(mn - sA[c*52+d]); sD[d*52+c] = v; sum += v; }
        const float inv = 1.f / sum;
        for (int d = 0; d < 48; d++) sD[d*52+c] *= inv;
    }
    for (int i = tid; i < 2304; i += 256) {
        const int co = i / 48, c = i - co*48;
        sB[co*52+c] = fuse_w[co*192 + s*48 + c];
    }
    __syncthreads();
    for (int i = tid; i < 2304; i += 256) {
        const int co = i / 48, d = i - co*48;
        sA[co*52+d] = dot48(&sB[co*52], &sD[d*52]);
    }
    __syncthreads();
    for (int i = tid; i < 2304; i += 256) {
        const int d = i / 48, e = i - d*48;
        sB[e*52+d] = sC[d*52+e];
    }
    __syncthreads();
    // P stored transposed [e][co] for scalar fuse
    for (int i = tid; i < 2304; i += 256) {
        const int co = i / 48, e = i - co*48;
        g_Pt[(((size_t)b*4 + s)*48 + e)*48 + co] = dot48(&sA[co*52], &sB[e*52]);
    }
}

// ---------------- pass C: fused 1x1 conv, scalar + register double-buffered staging (R11 proven) ----------------
__global__ __launch_bounds__(256) void k_fuse(const float* __restrict__ xa,
                                              const float* __restrict__ xb,
                                              const float* __restrict__ xc,
                                              const float* __restrict__ xd,
                                              const float* __restrict__ fuse_b) {
    __shared__ float sW[48][48];
    __shared__ float sX[24][256];
    __shared__ float sstats[96];
    const int b  = blockIdx.y;
    const int n0 = blockIdx.x * 256;
    const int tid = threadIdx.x, tx = tid & 31, ty = tid >> 5;

    if (tid < 96) sstats[tid] = 0.f;

    float acc[6][8];
    #pragma unroll
    for (int i = 0; i < 6; i++)
        #pragma unroll
        for (int j = 0; j < 8; j++) acc[i][j] = 0.f;

    const float* src[4] = {xa, xb, xc, xd};
    const size_t xbase = (size_t)b*48*NN + n0 + tid;
    const float* ptb = &g_Pt[(size_t)b*4*2304];

    float xr[24];
    #pragma unroll
    for (int k = 0; k < 24; k++) xr[k] = src[0][xbase + (size_t)k*NN];
    float wr[9];
    #pragma unroll
    for (int j = 0; j < 9; j++) wr[j] = ptb[tid + 256*j];

    for (int step = 0; step < 8; step++) {
        const int ch = step & 1, e0 = ch * 24;
        __syncthreads();
        if (ch == 0) {
            #pragma unroll
            for (int j = 0; j < 9; j++) sW[0][tid + 256*j] = wr[j];
        }
        #pragma unroll
        for (int k = 0; k < 24; k++) sX[k][tid] = xr[k];
        __syncthreads();
        if (step < 7) {
            const int ns = (step + 1) >> 1, nch = (step + 1) & 1, ne0 = nch * 24;
            const float* nf = src[ns];
            #pragma unroll
            for (int k = 0; k < 24; k++) xr[k] = nf[xbase + (size_t)(ne0 + k)*NN];
            if (nch == 0) {
                #pragma unroll
                for (int j = 0; j < 9; j++) wr[j] = ptb[ns*2304 + tid + 256*j];
            }
        }
        #pragma unroll 2
        for (int el = 0; el < 24; el++) {
            const float4 x0 = *(const float4*)&sX[el][4*tx];
            const float4 x1 = *(const float4*)&sX[el][4*tx + 128];
            #pragma unroll
            for (int i = 0; i < 6; i++) {
                const float wv = sW[e0 + el][ty + 8*i];
                acc[i][0] += wv*x0.x; acc[i][1] += wv*x0.y;
                acc[i][2] += wv*x0.z; acc[i][3] += wv*x0.w;
                acc[i][4] += wv*x1.x; acc[i][5] += wv*x1.y;
                acc[i][6] += wv*x1.z; acc[i][7] += wv*x1.w;
            }
        }
    }
    __syncthreads();

    #pragma unroll
    for (int i = 0; i < 6; i++) {
        const int co = ty + 8*i;
        const float fb_ = fuse_b[co];
        float4 o0, o1;
        o0.x = acc[i][0]+fb_; o0.y = acc[i][1]+fb_; o0.z = acc[i][2]+fb_; o0.w = acc[i][3]+fb_;
        o1.x = acc[i][4]+fb_; o1.y = acc[i][5]+fb_; o1.z = acc[i][6]+fb_; o1.w = acc[i][7]+fb_;
        float* row = &g_y1[((size_t)b*48 + co)*NN + n0];
        *(float4*)&row[4*tx]       = o0;
        *(float4*)&row[4*tx + 128] = o1;
        float lsum = o0.x+o0.y+o0.z+o0.w + o1.x+o1.y+o1.z+o1.w;
        float lsq  = o0.x*o0.x+o0.y*o0.y+o0.z*o0.z+o0.w*o0.w
                   + o1.x*o1.x+o1.y*o1.y+o1.z*o1.z+o1.w*o1.w;
        for (int o = 16; o > 0; o >>= 1) {
            lsum += __shfl_down_sync(0xffffffffu, lsum, o);
            lsq  += __shfl_down_sync(0xffffffffu, lsq,  o);
        }
        if (tx == 0) { atomicAdd(&sstats[co], lsum); atomicAdd(&sstats[48+co], lsq); }
    }
    __syncthreads();
    if (tid < 48) {
        atomicAdd(&g_stats[tid],      (double)sstats[tid]);
        atomicAdd(&g_stats[48 + tid], (double)sstats[48 + tid]);
    }
}

// ---------------- BN finalize (tiny) ----------------
__global__ void k_bnfin(const float* __restrict__ gamma, const float* __restrict__ beta, int which) {
    const int c = threadIdx.x;
    if (c >= 48) return;
    const double cnt  = (double)B * NN;
    const double mean = g_stats[which*96 + c] / cnt;
    const double var  = g_stats[which*96 + 48 + c] / cnt - mean*mean;
    const float  sc   = (float)((double)gamma[c] / sqrt(var + 1e-5));
    const float  sh   = beta[c] - (float)mean * sc;
    g_bn[which*96 + c]      = sc;
    g_bn[which*96 + 48 + c] = sh;
}

// ---------------- pass D: t = gamma_cam*relu(bn1(y1)) + input, in place; MLP-4 ----------------
__global__ void k_pre(const float* __restrict__ inp, const float* __restrict__ gamma_cam) {
    const size_t i = ((size_t)blockIdx.x * 256 + threadIdx.x) * 16;
    const int co = (int)((i / NN) % 48);     // NN % 16 == 0 -> uniform over the 16 floats
    const float sc = g_bn[co], sh = g_bn[48 + co];
    const float gcam = gamma_cam[0];
    float4 y[4], x[4];
    #pragma unroll
    for (int j = 0; j < 4; j++) y[j] = *(float4*)(g_y1 + i + 4*j);
    #pragma unroll
    for (int j = 0; j < 4; j++) x[j] = *(const float4*)(inp + i + 4*j);
    #pragma unroll
    for (int j = 0; j < 4; j++) {
        y[j].x = gcam * fmaxf(y[j].x*sc + sh, 0.f) + x[j].x;
        y[j].y = gcam * fmaxf(y[j].y*sc + sh, 0.f) + x[j].y;
        y[j].z = gcam * fmaxf(y[j].z*sc + sh, 0.f) + x[j].z;
        y[j].w = gcam * fmaxf(y[j].w*sc + sh, 0.f) + x[j].w;
        *(float4*)(g_y1 + i + 4*j) = y[j];
    }
}

// ---------------- pass E: 3x3 conv with register double-buffered staging (R11 proven) ----------------
__global__ __launch_bounds__(256) void k_conv(const float* __restrict__ out_w,
                                              const float* __restrict__ out_b,
                                              float* __restrict__ out) {
    __shared__ float sW[48*9];
    __shared__ float sT[10*34];
    __shared__ float ssum[48], ssq[48];
    const int b   = blockIdx.z;
    const int hy0 = blockIdx.y * 8;
    const int wx0 = blockIdx.x * 32;
    const int tid = threadIdx.x;
    const int cg  = tid >> 6;
    const int p   = tid & 63;
    const int px  = p & 31;
    const int py2 = p >> 5;

    if (tid < 48) { ssum[tid] = 0.f; ssq[tid] = 0.f; }

    const int r0 = tid / 34, c0 = tid - r0*34;
    const int gh0 = hy0 + r0 - 1, gw0 = wx0 + c0 - 1;
    const bool ok0 = (gh0 >= 0 && gh0 < HH && gw0 >= 0 && gw0 < WW) && (tid < 340);
    const int off0 = ok0 ? (gh0*WW + gw0) : 0;
    const int i1 = tid + 256;
    const int r1 = i1 / 34, c1 = i1 - r1*34;
    const int gh1 = hy0 + r1 - 1, gw1 = wx0 + c1 - 1;
    const bool ok1 = (i1 < 340) && (gh1 >= 0 && gh1 < HH && gw1 >= 0 && gw1 < WW);
    const int off1 = ok1 ? (gh1*WW + gw1) : 0;
    const bool st1 = (i1 < 340);
    const int wco0 = tid / 9, wk0 = tid - wco0*9;
    const int wbase0 = wco0*432 + wk0;
    const int wco1 = i1 / 9, wk1 = i1 - wco1*9;
    const int wbase1 = wco1*432 + wk1;
    const bool wok1 = (i1 < 432);

    const float* tbase = g_y1 + (size_t)b*48*NN;

    float t0 = ok0 ? tbase[off0] : 0.f;
    float t1 = ok1 ? tbase[off1] : 0.f;
    float w0 = out_w[wbase0];
    float w1 = wok1 ? out_w[wbase1] : 0.f;

    float acc[48];
    #pragma unroll
    for (int i = 0; i < 48; i++) acc[i] = 0.f;

    for (int ci = 0; ci < 48; ci++) {
        __syncthreads();
        if (tid < 340) sT[tid] = t0;
        if (st1)       sT[i1]  = t1;
        sW[tid] = w0;
        if (wok1) sW[i1] = w1;
        __syncthreads();
        if (ci < 47) {
            const float* tp = tbase + (size_t)(ci + 1)*NN;
            t0 = ok0 ? tp[off0] : 0.f;
            t1 = ok1 ? tp[off1] : 0.f;
            w0 = out_w[wbase0 + (ci + 1)*9];
            w1 = wok1 ? out_w[wbase1 + (ci + 1)*9] : 0.f;
        }

        float v[6][3];
        const int baseRow = py2 * 4;
        #pragma unroll
        for (int rr = 0; rr < 6; rr++)
            #pragma unroll
            for (int cc = 0; cc < 3; cc++)
                v[rr][cc] = sT[(baseRow + rr)*34 + px + cc];

        #pragma unroll
        for (int j = 0; j < 12; j++) {
            const float* wp = &sW[(cg*12 + j)*9];
            const float q0=wp[0],q1=wp[1],q2=wp[2],q3=wp[3],q4=wp[4],q5=wp[5],q6=wp[6],q7=wp[7],q8=wp[8];
            #pragma unroll
            for (int r = 0; r < 4; r++) {
                acc[j*4 + r] += q0*v[r  ][0] + q1*v[r  ][1] + q2*v[r  ][2]
                              + q3*v[r+1][0] + q4*v[r+1][1] + q5*v[r+1][2]
                              + q6*v[r+2][0] + q7*v[r+2][1] + q8*v[r+2][2];
            }
        }
    }

    #pragma unroll
    for (int j = 0; j < 12; j++) {
        const int co = cg*12 + j;
        const float bo = out_b[co];
        float lsum = 0.f, lsq = 0.f;
        #pragma unroll
        for (int r = 0; r < 4; r++) {
            const float val = acc[j*4 + r] + bo;
            const int gh = hy0 + py2*4 + r, gw = wx0 + px;
            out[((size_t)b*48 + co)*NN + gh*WW + gw] = val;
            lsum += val; lsq += val*val;
        }
        for (int o = 16; o > 0; o >>= 1) {
            lsum += __shfl_down_sync(0xffffffffu, lsum, o);
            lsq  += __shfl_down_sync(0xffffffffu, lsq,  o);
        }
        if ((tid & 31) == 0) { atomicAdd(&ssum[co], lsum); atomicAdd(&ssq[co], lsq); }
    }
    __syncthreads();
    if (tid < 48) {
        atomicAdd(&g_stats[96 + tid],  (double)ssum[tid]);
        atomicAdd(&g_stats[144 + tid], (double)ssq[tid]);
    }
}

// ---------------- pass G: in-place relu(bn2(y2)); MLP-4 ----------------
__global__ void k_final(float* __restrict__ out) {
    const size_t i = ((size_t)blockIdx.x * 256 + threadIdx.x) * 16;
    const int co = (int)((i / NN) % 48);
    const float sc = g_bn[96 + co], sh = g_bn[144 + co];
    float4 v[4];
    #pragma unroll
    for (int j = 0; j < 4; j++) v[j] = *(float4*)(out + i + 4*j);
    #pragma unroll
    for (int j = 0; j < 4; j++) {
        v[j].x = fmaxf(v[j].x*sc + sh, 0.f);
        v[j].y = fmaxf(v[j].y*sc + sh, 0.f);
        v[j].z = fmaxf(v[j].z*sc + sh, 0.f);
        v[j].w = fmaxf(v[j].w*sc + sh, 0.f);
        *(float4*)(out + i + 4*j) = v[j];
    }
}

// ---------------- launch ----------------
extern "C" void kernel_launch(void* const* d_in, const int* in_sizes, int n_in,
                              void* d_out, int out_size) {
    const float* xa         = (const float*)d_in[0];
    const float* fb         = (const float*)d_in[1];
    const float* fc         = (const float*)d_in[2];
    const float* fd         = (const float*)d_in[3];
    const float* Wa         = (const float*)d_in[4];
    const float* Wb         = (const float*)d_in[5];
    const float* Wc         = (const float*)d_in[6];
    const float* Wd         = (const float*)d_in[7];
    const float* fuse_w     = (const float*)d_in[8];
    const float* fuse_b     = (const float*)d_in[9];
    const float* fuse_gamma = (const float*)d_in[10];
    const float* fuse_beta  = (const float*)d_in[11];
    const float* gamma_cam  = (const float*)d_in[12];
    const float* out_w      = (const float*)d_in[13];
    const float* out_b      = (const float*)d_in[14];
    const float* out_gamma  = (const float*)d_in[15];
    const float* out_beta   = (const float*)d_in[16];
    float* out = (float*)d_out;

    k_zero<<<288, 256>>>();
    k_gram<<<dim3(16, B), 384>>>(xa, fb, fc, fd);
    k_attn<<<dim3(4, B), 256>>>(Wa, Wb, Wc, Wd, fuse_w);
    k_fuse<<<dim3(NN/256, B), 256>>>(xa, fb, fc, fd, fuse_b);
    k_bnfin<<<1, 48>>>(fuse_gamma, fuse_beta, 0);
    k_pre<<<(B*C*NN)/4096, 256>>>(xa, gamma_cam);
    k_conv<<<dim3(WW/32, HH/8, B), 256>>>(out_w, out_b, out);
    k_bnfin<<<1, 48>>>(out_gamma, out_beta, 1);
    k_final<<<(B*C*NN)/4096, 256>>>(out);
}

// round 17
// speedup vs baseline: 1.0420x; 1.0285x over previous
#include <cuda_runtime.h>
#include <math.h>

#define B  8
#define C  48
#define HH 192
#define WW 192
#define NN (HH*WW)   // 36864

// ---------------- scratch (no allocations allowed) ----------------
__device__ float  g_G[4*B*C*C];        // Gram matrices  [s][b][c][d]
__device__ float  g_Pt[B*4*C*C];       // P transposed   [b][s][e][co]
__device__ float  g_y1[B*C*NN];        // fuse output; overwritten with t by k_pre
__device__ double g_stats[4*C];        // sum1, sq1, sum2, sq2
__device__ float  g_bn[4*C];           // scale1, shift1, scale2, shift2

__device__ __forceinline__ float dot48(const float* __restrict__ a, const float* __restrict__ b) {
    float s = 0.f;
    #pragma unroll
    for (int k = 0; k < 12; k++) {
        const float4 x = ((const float4*)a)[k];
        const float4 y = ((const float4*)b)[k];
        s += x.x*y.x + x.y*y.y + x.z*y.z + x.w*y.w;
    }
    return s;
}

// ---------------- tf32 helpers (verified R7/R14) ----------------
__device__ __forceinline__ void split_tf32(float x, unsigned& hi, unsigned& lo) {
    unsigned h;
    asm("cvt.rna.tf32.f32 %0, %1;" : "=r"(h) : "f"(x));
    float r = x - __uint_as_float(h);
    unsigned l;
    asm("cvt.rna.tf32.f32 %0, %1;" : "=r"(l) : "f"(r));
    hi = h; lo = l;
}
__device__ __forceinline__ void mma_tf32(float d[4], const unsigned a[4], const unsigned b[2]) {
    asm volatile(
        "mma.sync.aligned.m16n8k8.row.col.f32.tf32.tf32.f32 "
        "{%0,%1,%2,%3}, {%4,%5,%6,%7}, {%8,%9}, {%0,%1,%2,%3};"
        : "+f"(d[0]), "+f"(d[1]), "+f"(d[2]), "+f"(d[3])
        : "r"(a[0]), "r"(a[1]), "r"(a[2]), "r"(a[3]), "r"(b[0]), "r"(b[1]));
}

// ---------------- zero scratch ----------------
__global__ void k_zero() {
    int i = blockIdx.x * 256 + threadIdx.x;
    if (i < 4*B*C*C) g_G[i] = 0.f;
    if (i < 4*C)     g_stats[i] = 0.0;
}

// ---------------- pass A: Gram via tf32 mma.sync (R14 proven) ----------------
__global__ __launch_bounds__(384) void k_gram(const float* __restrict__ xa,
                                              const float* __restrict__ xb,
                                              const float* __restrict__ xc,
                                              const float* __restrict__ xd) {
    __shared__ float sX[4*48*52];   // 39936 B
    const int b     = blockIdx.y;
    const int chunk = blockIdx.x;   // 16 chunks of 2304
    const int tid  = threadIdx.x;
    const int warp = tid >> 5, lane = tid & 31;
    const int g = lane >> 2, t = lane & 3;
    const int s   = warp / 3;
    const int nt2 = (warp - s*3) * 2;

    float acc[3][2][4];
    #pragma unroll
    for (int m = 0; m < 3; m++)
        #pragma unroll
        for (int j = 0; j < 2; j++)
            #pragma unroll
            for (int k = 0; k < 4; k++) acc[m][j][k] = 0.f;

    const size_t base = (size_t)b * C * NN + (size_t)chunk * 2304;
    const float* src[4] = {xa, xb, xc, xd};

    float r[24];
    #pragma unroll
    for (int k = 0; k < 24; k++) {
        const int idx = tid + 384*k;
        const int s2 = idx / 2304, rem = idx - s2*2304;
        const int c = rem / 48, nl = rem - c*48;
        r[k] = src[s2][base + (size_t)c * NN + nl];
    }

    const float* A  = sX;
    const float* Bm = sX + s*2496;

    for (int tile = 0; tile < 48; tile++) {
        __syncthreads();
        #pragma unroll
        for (int k = 0; k < 24; k++) {
            const int idx = tid + 384*k;
            const int s2 = idx / 2304, rem = idx - s2*2304;
            const int c = rem / 48, nl = rem - c*48;
            sX[(s2*48 + c)*52 + nl] = r[k];
        }
        __syncthreads();
        if (tile < 47) {
            const int n0 = (tile + 1) * 48;
            #pragma unroll
            for (int k = 0; k < 24; k++) {
                const int idx = tid + 384*k;
                const int s2 = idx / 2304, rem = idx - s2*2304;
                const int c = rem / 48, nl = rem - c*48;
                r[k] = src[s2][base + (size_t)c * NN + n0 + nl];
            }
        }
        for (int k8 = 0; k8 < 6; k8++) {
            const int k0 = k8 * 8;
            unsigned ahi[3][4], alo[3][4];
            #pragma unroll
            for (int m = 0; m < 3; m++) {
                split_tf32(A[(16*m + g    )*52 + k0 + t    ], ahi[m][0], alo[m][0]);
                split_tf32(A[(16*m + g + 8)*52 + k0 + t    ], ahi[m][1], alo[m][1]);
                split_tf32(A[(16*m + g    )*52 + k0 + t + 4], ahi[m][2], alo[m][2]);
                split_tf32(A[(16*m + g + 8)*52 + k0 + t + 4], ahi[m][3], alo[m][3]);
            }
            unsigned bhi[2][2], blo[2][2];
            #pragma unroll
            for (int j = 0; j < 2; j++) {
                const int dr = 8*(nt2 + j) + g;
                split_tf32(Bm[dr*52 + k0 + t    ], bhi[j][0], blo[j][0]);
                split_tf32(Bm[dr*52 + k0 + t + 4], bhi[j][1], blo[j][1]);
            }
            #pragma unroll
            for (int m = 0; m < 3; m++)
                #pragma unroll
                for (int j = 0; j < 2; j++) {
                    mma_tf32(acc[m][j], alo[m], bhi[j]);
                    mma_tf32(acc[m][j], ahi[m], blo[j]);
                    mma_tf32(acc[m][j], ahi[m], bhi[j]);
                }
        }
    }
    #pragma unroll
    for (int m = 0; m < 3; m++)
        #pragma unroll
        for (int j = 0; j < 2; j++) {
            const int c0 = 16*m + g;
            const int d0 = 8*(nt2 + j) + 2*t;
            float* Gp = &g_G[((size_t)(s*B + b)*48)*48];
            atomicAdd(&Gp[ c0     *48 + d0    ], acc[m][j][0]);
            atomicAdd(&Gp[ c0     *48 + d0 + 1], acc[m][j][1]);
            atomicAdd(&Gp[(c0 + 8)*48 + d0    ], acc[m][j][2]);
            atomicAdd(&Gp[(c0 + 8)*48 + d0 + 1], acc[m][j][3]);
        }
}

// ---------------- pass B: energy -> attention -> M -> P — float4 inner-product version ----------------
__global__ __launch_bounds__(256) void k_attn(const float* __restrict__ Wa,
                                              const float* __restrict__ Wb,
                                              const float* __restrict__ Wc,
                                              const float* __restrict__ Wd,
                                              const float* __restrict__ fuse_w) {
    __shared__ float sA[48*52];
    __shared__ float sB[48*52];
    __shared__ float sC[48*52];
    __shared__ float sD[48*52];
    const int s = blockIdx.x, b = blockIdx.y, tid = threadIdx.x;
    const float* Wsp = (s == 0) ? Wa : (s == 1) ? Wb : (s == 2) ? Wc : Wd;

    for (int i = tid; i < 2304; i += 256) {
        const int r = i / 48, q = i - r*48;
        sA[r*52+q] = g_G[(s*B + b)*2304 + i];
        sB[r*52+q] = Wa[i];
        sC[r*52+q] = Wsp[i];
    }
    __syncthreads();
    for (int i = tid; i < 2304; i += 256) {
        const int e = i / 48, d = i - e*48;
        sD[d*52+e] = dot48(&sA[e*52], &sC[d*52]);
    }
    __syncthreads();
    for (int i = tid; i < 2304; i += 256) {
        const int c = i / 48, d = i - c*48;
        sA[c*52+d] = dot48(&sB[c*52], &sD[d*52]);
    }
    __syncthreads();
    if (tid < 48) {
        const int c = tid;
        float mn = sA[c*52];
        for (int d = 1; d < 48; d++) mn = fminf(mn, sA[c*52+d]);
        float sum = 0.f;
        for (int d = 0; d < 48; d++) { const float v = expf(mn - sA[c*52+d]); sD[d*52+c] = v; sum += v; }
        const float inv = 1.f / sum;
        for (int d = 0; d < 48; d++) sD[d*52+c] *= inv;
    }
    for (int i = tid; i < 2304; i += 256) {
        const int co = i / 48, c = i - co*48;
        sB[co*52+c] = fuse_w[co*192 + s*48 + c];
    }
    __syncthreads();
    for (int i = tid; i < 2304; i += 256) {
        const int co = i / 48, d = i - co*48;
        sA[co*52+d] = dot48(&sB[co*52], &sD[d*52]);
    }
    __syncthreads();
    for (int i = tid; i < 2304; i += 256) {
        const int d = i / 48, e = i - d*48;
        sB[e*52+d] = sC[d*52+e];
    }
    __syncthreads();
    // P stored transposed [e][co] for scalar fuse
    for (int i = tid; i < 2304; i += 256) {
        const int co = i / 48, e = i - co*48;
        g_Pt[(((size_t)b*4 + s)*48 + e)*48 + co] = dot48(&sA[co*52], &sB[e*52]);
    }
}

// ---------------- pass C: fused 1x1 conv, scalar + register double-buffered staging (R11 proven) ----------------
__global__ __launch_bounds__(256) void k_fuse(const float* __restrict__ xa,
                                              const float* __restrict__ xb,
                                              const float* __restrict__ xc,
                                              const float* __restrict__ xd,
                                              const float* __restrict__ fuse_b) {
    __shared__ float sW[48][48];
    __shared__ float sX[24][256];
    __shared__ float sstats[96];
    const int b  = blockIdx.y;
    const int n0 = blockIdx.x * 256;
    const int tid = threadIdx.x, tx = tid & 31, ty = tid >> 5;

    if (tid < 96) sstats[tid] = 0.f;

    float acc[6][8];
    #pragma unroll
    for (int i = 0; i < 6; i++)
        #pragma unroll
        for (int j = 0; j < 8; j++) acc[i][j] = 0.f;

    const float* src[4] = {xa, xb, xc, xd};
    const size_t xbase = (size_t)b*48*NN + n0 + tid;
    const float* ptb = &g_Pt[(size_t)b*4*2304];

    float xr[24];
    #pragma unroll
    for (int k = 0; k < 24; k++) xr[k] = src[0][xbase + (size_t)k*NN];
    float wr[9];
    #pragma unroll
    for (int j = 0; j < 9; j++) wr[j] = ptb[tid + 256*j];

    for (int step = 0; step < 8; step++) {
        const int ch = step & 1, e0 = ch * 24;
        __syncthreads();
        if (ch == 0) {
            #pragma unroll
            for (int j = 0; j < 9; j++) sW[0][tid + 256*j] = wr[j];
        }
        #pragma unroll
        for (int k = 0; k < 24; k++) sX[k][tid] = xr[k];
        __syncthreads();
        if (step < 7) {
            const int ns = (step + 1) >> 1, nch = (step + 1) & 1, ne0 = nch * 24;
            const float* nf = src[ns];
            #pragma unroll
            for (int k = 0; k < 24; k++) xr[k] = nf[xbase + (size_t)(ne0 + k)*NN];
            if (nch == 0) {
                #pragma unroll
                for (int j = 0; j < 9; j++) wr[j] = ptb[ns*2304 + tid + 256*j];
            }
        }
        #pragma unroll 2
        for (int el = 0; el < 24; el++) {
            const float4 x0 = *(const float4*)&sX[el][4*tx];
            const float4 x1 = *(const float4*)&sX[el][4*tx + 128];
            #pragma unroll
            for (int i = 0; i < 6; i++) {
                const float wv = sW[e0 + el][ty + 8*i];
                acc[i][0] += wv*x0.x; acc[i][1] += wv*x0.y;
                acc[i][2] += wv*x0.z; acc[i][3] += wv*x0.w;
                acc[i][4] += wv*x1.x; acc[i][5] += wv*x1.y;
                acc[i][6] += wv*x1.z; acc[i][7] += wv*x1.w;
            }
        }
    }
    __syncthreads();

    #pragma unroll
    for (int i = 0; i < 6; i++) {
        const int co = ty + 8*i;
        const float fb_ = fuse_b[co];
        float4 o0, o1;
        o0.x = acc[i][0]+fb_; o0.y = acc[i][1]+fb_; o0.z = acc[i][2]+fb_; o0.w = acc[i][3]+fb_;
        o1.x = acc[i][4]+fb_; o1.y = acc[i][5]+fb_; o1.z = acc[i][6]+fb_; o1.w = acc[i][7]+fb_;
        float* row = &g_y1[((size_t)b*48 + co)*NN + n0];
        *(float4*)&row[4*tx]       = o0;
        *(float4*)&row[4*tx + 128] = o1;
        float lsum = o0.x+o0.y+o0.z+o0.w + o1.x+o1.y+o1.z+o1.w;
        float lsq  = o0.x*o0.x+o0.y*o0.y+o0.z*o0.z+o0.w*o0.w
                   + o1.x*o1.x+o1.y*o1.y+o1.z*o1.z+o1.w*o1.w;
        for (int o = 16; o > 0; o >>= 1) {
            lsum += __shfl_down_sync(0xffffffffu, lsum, o);
            lsq  += __shfl_down_sync(0xffffffffu, lsq,  o);
        }
        if (tx == 0) { atomicAdd(&sstats[co], lsum); atomicAdd(&sstats[48+co], lsq); }
    }
    __syncthreads();
    if (tid < 48) {
        atomicAdd(&g_stats[tid],      (double)sstats[tid]);
        atomicAdd(&g_stats[48 + tid], (double)sstats[48 + tid]);
    }
}

// ---------------- BN finalize (tiny) ----------------
__global__ void k_bnfin(const float* __restrict__ gamma, const float* __restrict__ beta, int which) {
    const int c = threadIdx.x;
    if (c >= 48) return;
    const double cnt  = (double)B * NN;
    const double mean = g_stats[which*96 + c] / cnt;
    const double var  = g_stats[which*96 + 48 + c] / cnt - mean*mean;
    const float  sc   = (float)((double)gamma[c] / sqrt(var + 1e-5));
    const float  sh   = beta[c] - (float)mean * sc;
    g_bn[which*96 + c]      = sc;
    g_bn[which*96 + 48 + c] = sh;
}

// ---------------- pass D: t = gamma_cam*relu(bn1(y1)) + input; coalesced MLP-4 ----------------
// block owns 4096 consecutive floats (4096 | NN -> co uniform); thread t: float4 at t*4 + j*1024
__global__ void k_pre(const float* __restrict__ inp, const float* __restrict__ gamma_cam) {
    const size_t base = (size_t)blockIdx.x * 4096 + threadIdx.x * 4;
    const int co = (int)(((size_t)blockIdx.x * 4096 / NN) % 48);
    const float sc = g_bn[co], sh = g_bn[48 + co];
    const float gcam = gamma_cam[0];
    float4 y[4], x[4];
    #pragma unroll
    for (int j = 0; j < 4; j++) y[j] = *(float4*)(g_y1 + base + j*1024);
    #pragma unroll
    for (int j = 0; j < 4; j++) x[j] = *(const float4*)(inp + base + j*1024);
    #pragma unroll
    for (int j = 0; j < 4; j++) {
        y[j].x = gcam * fmaxf(y[j].x*sc + sh, 0.f) + x[j].x;
        y[j].y = gcam * fmaxf(y[j].y*sc + sh, 0.f) + x[j].y;
        y[j].z = gcam * fmaxf(y[j].z*sc + sh, 0.f) + x[j].z;
        y[j].w = gcam * fmaxf(y[j].w*sc + sh, 0.f) + x[j].w;
        *(float4*)(g_y1 + base + j*1024) = y[j];
    }
}

// ---------------- pass E: 3x3 conv with register double-buffered staging (R11 proven) ----------------
__global__ __launch_bounds__(256) void k_conv(const float* __restrict__ out_w,
                                              const float* __restrict__ out_b,
                                              float* __restrict__ out) {
    __shared__ float sW[48*9];
    __shared__ float sT[10*34];
    __shared__ float ssum[48], ssq[48];
    const int b   = blockIdx.z;
    const int hy0 = blockIdx.y * 8;
    const int wx0 = blockIdx.x * 32;
    const int tid = threadIdx.x;
    const int cg  = tid >> 6;
    const int p   = tid & 63;
    const int px  = p & 31;
    const int py2 = p >> 5;

    if (tid < 48) { ssum[tid] = 0.f; ssq[tid] = 0.f; }

    const int r0 = tid / 34, c0 = tid - r0*34;
    const int gh0 = hy0 + r0 - 1, gw0 = wx0 + c0 - 1;
    const bool ok0 = (gh0 >= 0 && gh0 < HH && gw0 >= 0 && gw0 < WW) && (tid < 340);
    const int off0 = ok0 ? (gh0*WW + gw0) : 0;
    const int i1 = tid + 256;
    const int r1 = i1 / 34, c1 = i1 - r1*34;
    const int gh1 = hy0 + r1 - 1, gw1 = wx0 + c1 - 1;
    const bool ok1 = (i1 < 340) && (gh1 >= 0 && gh1 < HH && gw1 >= 0 && gw1 < WW);
    const int off1 = ok1 ? (gh1*WW + gw1) : 0;
    const bool st1 = (i1 < 340);
    const int wco0 = tid / 9, wk0 = tid - wco0*9;
    const int wbase0 = wco0*432 + wk0;
    const int wco1 = i1 / 9, wk1 = i1 - wco1*9;
    const int wbase1 = wco1*432 + wk1;
    const bool wok1 = (i1 < 432);

    const float* tbase = g_y1 + (size_t)b*48*NN;

    float t0 = ok0 ? tbase[off0] : 0.f;
    float t1 = ok1 ? tbase[off1] : 0.f;
    float w0 = out_w[wbase0];
    float w1 = wok1 ? out_w[wbase1] : 0.f;

    float acc[48];
    #pragma unroll
    for (int i = 0; i < 48; i++) acc[i] = 0.f;

    for (int ci = 0; ci < 48; ci++) {
        __syncthreads();
        if (tid < 340) sT[tid] = t0;
        if (st1)       sT[i1]  = t1;
        sW[tid] = w0;
        if (wok1) sW[i1] = w1;
        __syncthreads();
        if (ci < 47) {
            const float* tp = tbase + (size_t)(ci + 1)*NN;
            t0 = ok0 ? tp[off0] : 0.f;
            t1 = ok1 ? tp[off1] : 0.f;
            w0 = out_w[wbase0 + (ci + 1)*9];
            w1 = wok1 ? out_w[wbase1 + (ci + 1)*9] : 0.f;
        }

        float v[6][3];
        const int baseRow = py2 * 4;
        #pragma unroll
        for (int rr = 0; rr < 6; rr++)
            #pragma unroll
            for (int cc = 0; cc < 3; cc++)
                v[rr][cc] = sT[(baseRow + rr)*34 + px + cc];

        #pragma unroll
        for (int j = 0; j < 12; j++) {
            const float* wp = &sW[(cg*12 + j)*9];
            const float q0=wp[0],q1=wp[1],q2=wp[2],q3=wp[3],q4=wp[4],q5=wp[5],q6=wp[6],q7=wp[7],q8=wp[8];
            #pragma unroll
            for (int r = 0; r < 4; r++) {
                acc[j*4 + r] += q0*v[r  ][0] + q1*v[r  ][1] + q2*v[r  ][2]
                              + q3*v[r+1][0] + q4*v[r+1][1] + q5*v[r+1][2]
                              + q6*v[r+2][0] + q7*v[r+2][1] + q8*v[r+2][2];
            }
        }
    }

    #pragma unroll
    for (int j = 0; j < 12; j++) {
        const int co = cg*12 + j;
        const float bo = out_b[co];
        float lsum = 0.f, lsq = 0.f;
        #pragma unroll
        for (int r = 0; r < 4; r++) {
            const float val = acc[j*4 + r] + bo;
            const int gh = hy0 + py2*4 + r, gw = wx0 + px;
            out[((size_t)b*48 + co)*NN + gh*WW + gw] = val;
            lsum += val; lsq += val*val;
        }
        for (int o = 16; o > 0; o >>= 1) {
            lsum += __shfl_down_sync(0xffffffffu, lsum, o);
            lsq  += __shfl_down_sync(0xffffffffu, lsq,  o);
        }
        if ((tid & 31) == 0) { atomicAdd(&ssum[co], lsum); atomicAdd(&ssq[co], lsq); }
    }
    __syncthreads();
    if (tid < 48) {
        atomicAdd(&g_stats[96 + tid],  (double)ssum[tid]);
        atomicAdd(&g_stats[144 + tid], (double)ssq[tid]);
    }
}

// ---------------- pass G: in-place relu(bn2(y2)); coalesced MLP-4 ----------------
__global__ void k_final(float* __restrict__ out) {
    const size_t base = (size_t)blockIdx.x * 4096 + threadIdx.x * 4;
    const int co = (int)(((size_t)blockIdx.x * 4096 / NN) % 48);
    const float sc = g_bn[96 + co], sh = g_bn[144 + co];
    float4 v[4];
    #pragma unroll
    for (int j = 0; j < 4; j++) v[j] = *(float4*)(out + base + j*1024);
    #pragma unroll
    for (int j = 0; j < 4; j++) {
        v[j].x = fmaxf(v[j].x*sc + sh, 0.f);
        v[j].y = fmaxf(v[j].y*sc + sh, 0.f);
        v[j].z = fmaxf(v[j].z*sc + sh, 0.f);
        v[j].w = fmaxf(v[j].w*sc + sh, 0.f);
        *(float4*)(out + base + j*1024) = v[j];
    }
}

// ---------------- launch ----------------
extern "C" void kernel_launch(void* const* d_in, const int* in_sizes, int n_in,
                              void* d_out, int out_size) {
    const float* xa         = (const float*)d_in[0];
    const float* fb         = (const float*)d_in[1];
    const float* fc         = (const float*)d_in[2];
    const float* fd         = (const float*)d_in[3];
    const float* Wa         = (const float*)d_in[4];
    const float* Wb         = (const float*)d_in[5];
    const float* Wc         = (const float*)d_in[6];
    const float* Wd         = (const float*)d_in[7];
    const float* fuse_w     = (const float*)d_in[8];
    const float* fuse_b     = (const float*)d_in[9];
    const float* fuse_gamma = (const float*)d_in[10];
    const float* fuse_beta  = (const float*)d_in[11];
    const float* gamma_cam  = (const float*)d_in[12];
    const float* out_w      = (const float*)d_in[13];
    const float* out_b      = (const float*)d_in[14];
    const float* out_gamma  = (const float*)d_in[15];
    const float* out_beta   = (const float*)d_in[16];
    float* out = (float*)d_out;

    k_zero<<<288, 256>>>();
    k_gram<<<dim3(16, B), 384>>>(xa, fb, fc, fd);
    k_attn<<<dim3(4, B), 256>>>(Wa, Wb, Wc, Wd, fuse_w);
    k_fuse<<<dim3(NN/256, B), 256>>>(xa, fb, fc, fd, fuse_b);
    k_bnfin<<<1, 48>>>(fuse_gamma, fuse_beta, 0);
    k_pre<<<(B*C*NN)/4096, 256>>>(xa, gamma_cam);
    k_conv<<<dim3(WW/32, HH/8, B), 256>>>(out_w, out_b, out);
    k_bnfin<<<1, 48>>>(out_gamma, out_beta, 1);
    k_final<<<(B*C*NN)/4096, 256>>>(out);
}